// round 12
// baseline (speedup 1.0000x reference)
#include <cuda_runtime.h>
#include <math.h>

#define THREADS 128
#define JT      256
#define RPT     4            // rows per thread; block covers THREADS*RPT = 512 rows

typedef unsigned long long ull;

// 12 fp64 accumulator slots: job*4 + (b&3). Zero-initialized at module load;
// the last block resets them after reading so every graph replay starts from 0.
__device__ double   g_acc[12];
__device__ unsigned g_ticket = 0;

__device__ __forceinline__ float ex2f(float v) {
    float y;
    asm("ex2.approx.ftz.f32 %0, %1;" : "=f"(y) : "f"(v));
    return y;
}

// 10-bit LUT exp2: s <= ~0, returns ~2^s. Error +-3.4e-4 per term, random
// (averages out in the 32M-term sums; bias ~5e-9). Runs on fma/alu/LDS pipes,
// zero MUFU. T[j] = float bits of 2^(j/1024).
__device__ __forceinline__ float lutexp(float s, const unsigned* __restrict__ T) {
    s = fmaxf(s, -126.0f);                      // keep k<<23 in float range
    float t = fmaf(s, 1024.0f, 12582912.0f);    // 1.5*2^23: fixed-point round
    unsigned tb = __float_as_uint(t);           // = 0x4B400000 + round(s*1024)
    unsigned j  = tb & 1023u;                   // fraction index
    unsigned kb = (tb & ~1023u) << 13;          // = k<<23 (mod 2^32), exact
    return __uint_as_float(T[j] + kb);
}

__device__ __forceinline__ void red_relaxed_f64(double* p, double v) {
    asm volatile("red.relaxed.gpu.global.add.f64 [%0], %1;" :: "l"(p), "d"(v) : "memory");
}
__device__ __forceinline__ unsigned atom_acqrel_inc(unsigned* p) {
    unsigned old;
    asm volatile("atom.acq_rel.gpu.global.add.u32 %0, [%1], 1;"
                 : "=r"(old) : "l"(p) : "memory");
    return old;
}

// Single fused kernel; grid enumerates ONLY non-empty tiles -> one balanced wave
// (1056 blocks). Job 0: xz (all tiles). Jobs 1/2 (xx, zz): upper-wedge tiles
// (js >= 2*it). Full tiles: 6 exps/iter via MUFU + 2 via smem LUT.
__global__ void __launch_bounds__(THREADS) pair_kernel(
    const float* __restrict__ x, const float* __restrict__ z,
    const float* __restrict__ ks, const float* __restrict__ theta,
    float* __restrict__ out, int n)
{
    const int iTiles = n / (THREADS * RPT);   // 16
    const int jSlabs = n / JT;                // 32
    const int tpj = iTiles * jSlabs;          // 512
    const int wedge = iTiles * (jSlabs + 1 - iTiles);   // 272

    const int b = blockIdx.x;
    const int tid = threadIdx.x;

    int job, it, js;
    if (b < tpj) {
        job = 0;
        it = b % iTiles;
        js = b / iTiles;
    } else {
        int u = b - tpj;
        job = 1 + u / wedge;
        u -= (job - 1) * wedge;
        int itv = 0;
        while (true) {
            int nb = (itv + 1) * (jSlabs + 1 - (itv + 1));
            if (nb > u) break;
            itv++;
        }
        it = itv;
        js = 2 * it + (u - it * (jSlabs + 1 - it));
    }

    // ---- Passthrough copy: out[0..3n) = x, out[3n..6n) = z, sliced by block ----
    {
        const int total = 6 * n;
        const int per = (total + gridDim.x - 1) / gridDim.x;
        const int start = b * per;
        const int stop = min(start + per, total);
        for (int idx = start + tid; idx < stop; idx += THREADS)
            out[idx] = (idx < 3 * n) ? x[idx] : z[idx - 3 * n];
    }

    const bool sym = (job >= 1);
    const int i0 = it * THREADS * RPT;
    const int j0 = js * JT;

    const float* A = (job == 2) ? z : x;
    const float* B = (job == 1) ? x : z;

    const float sc = sqrtf(1.4426950408889634f / ks[0]);   // sqrt(log2e / ks)

    // B slab (packed-pairs layout for f32x2) + exp2 fraction table.
    __shared__ float4   sB[JT];
    __shared__ unsigned sT[1024];
    for (int g = tid; g < JT / 2; g += THREADS) {
        int ja = j0 + 2 * g, jb = ja + 1;
        float b0x = B[3 * ja]     * sc, b0y = B[3 * ja + 1] * sc, b0z = B[3 * ja + 2] * sc;
        float b1x = B[3 * jb]     * sc, b1y = B[3 * jb + 1] * sc, b1z = B[3 * jb + 2] * sc;
        float w0 = -(b0x * b0x + b0y * b0y + b0z * b0z);
        float w1 = -(b1x * b1x + b1y * b1y + b1z * b1z);
        sB[2 * g]     = make_float4(b0x, b1x, b0y, b1y);
        sB[2 * g + 1] = make_float4(b0z, b1z, w0, w1);
    }
    for (int j = tid; j < 1024; j += THREADS)
        sT[j] = __float_as_uint(exp2f((float)j * (1.0f / 1024.0f)));

    // Four rows per thread: r = i0 + tid + {0,1,2,3}*THREADS.
    float ax[RPT], ay[RPT], az[RPT], aw[RPT];
#pragma unroll
    for (int rr = 0; rr < RPT; rr++) {
        int r = i0 + tid + rr * THREADS;
        ax[rr] = A[3 * r]     * sc * 2.f;
        ay[rr] = A[3 * r + 1] * sc * 2.f;
        az[rr] = A[3 * r + 2] * sc * 2.f;
        aw[rr] = -0.25f * (ax[rr] * ax[rr] + ay[rr] * ay[rr] + az[rr] * az[rr]);
    }
    __syncthreads();

    float acc[RPT][2];
#pragma unroll
    for (int rr = 0; rr < RPT; rr++) { acc[rr][0] = 0.f; acc[rr][1] = 0.f; }

    const bool boundary = sym && (js == 2 * it || js == 2 * it + 1);

    if (!boundary) {
        // Full tile: 2 cols x 4 rows per iteration. Rows 0-2 -> MUFU, row 3 -> LUT.
        ull axp[RPT], ayp[RPT], azp[RPT];
#pragma unroll
        for (int rr = 0; rr < RPT; rr++) {
            asm("mov.b64 %0, {%1,%1};" : "=l"(axp[rr]) : "f"(ax[rr]));
            asm("mov.b64 %0, {%1,%1};" : "=l"(ayp[rr]) : "f"(ay[rr]));
            asm("mov.b64 %0, {%1,%1};" : "=l"(azp[rr]) : "f"(az[rr]));
        }
        unsigned sb = (unsigned)__cvta_generic_to_shared(sB);
#pragma unroll 8
        for (int k2 = 0; k2 < JT / 2; k2++) {
            ull p0, p1, q0, q1;
            asm("ld.shared.v2.u64 {%0,%1},[%2];" : "=l"(p0), "=l"(p1) : "r"(sb + k2 * 32));
            asm("ld.shared.v2.u64 {%0,%1},[%2];" : "=l"(q0), "=l"(q1) : "r"(sb + k2 * 32 + 16));
            ull sv[RPT];
#pragma unroll
            for (int rr = 0; rr < RPT; rr++) {
                asm("fma.rn.f32x2 %0,%1,%2,%3;" : "=l"(sv[rr]) : "l"(axp[rr]), "l"(p0), "l"(q1));
                asm("fma.rn.f32x2 %0,%1,%2,%0;" : "+l"(sv[rr]) : "l"(ayp[rr]), "l"(p1));
                asm("fma.rn.f32x2 %0,%1,%2,%0;" : "+l"(sv[rr]) : "l"(azp[rr]), "l"(q0));
            }
#pragma unroll
            for (int rr = 0; rr < 3; rr++) {
                float h0, h1;
                asm("mov.b64 {%0,%1}, %2;" : "=f"(h0), "=f"(h1) : "l"(sv[rr]));
                acc[rr][0] += ex2f(h0);
                acc[rr][1] += ex2f(h1);
            }
            {
                float h0, h1;
                asm("mov.b64 {%0,%1}, %2;" : "=f"(h0), "=f"(h1) : "l"(sv[3]));
                acc[3][0] += lutexp(h0, sT);
                acc[3][1] += lutexp(h1, sT);
            }
        }
    } else {
        // Boundary tiles (64 of 1056), scalar all-MUFU loop with row predicates.
        // js==2it   : row0 keep k>tid, row1 keep k>tid+128, rows 2,3 skip.
        // js==2it+1 : rows 0,1 keep all, row2 keep k>tid, row3 keep k>tid+128.
        const bool lower = (js == 2 * it);
        const float* f = (const float*)sB;
#pragma unroll 4
        for (int k = 0; k < JT; k++) {
            int k2 = k >> 1, l = k & 1;
            float bx = f[8 * k2 + l];
            float by = f[8 * k2 + 2 + l];
            float bz = f[8 * k2 + 4 + l];
            float bw = f[8 * k2 + 6 + l];
            float e[RPT];
#pragma unroll
            for (int rr = 0; rr < RPT; rr++) {
                float s = fmaf(ax[rr], bx, bw);
                s = fmaf(ay[rr], by, s);
                s = fmaf(az[rr], bz, s);
                e[rr] = ex2f(s);
            }
            if (lower) {
                if (k > tid)       acc[0][0] += e[0];
                if (k > tid + 128) acc[1][0] += e[1];
            } else {
                acc[0][0] += e[0];
                acc[1][0] += e[1];
                if (k > tid)       acc[2][0] += e[2];
                if (k > tid + 128) acc[3][0] += e[3];
            }
        }
    }

    // Per-row factor 2^{aw}, then block reduce -> one fp64 RED per block.
    float accT = 0.f;
#pragma unroll
    for (int rr = 0; rr < RPT; rr++)
        accT += (acc[rr][0] + acc[rr][1]) * ex2f(aw[rr]);
#pragma unroll
    for (int o = 16; o > 0; o >>= 1) accT += __shfl_xor_sync(0xffffffffu, accT, o);
    __shared__ float ws[THREADS / 32];
    const int lane = tid & 31;
    const int wid = tid >> 5;
    if (lane == 0) ws[wid] = accT;
    __syncthreads();
    if (tid == 0) {
        float s = 0.f;
#pragma unroll
        for (int w = 0; w < THREADS / 32; w++) s += ws[w];
        red_relaxed_f64(&g_acc[job * 4 + (b & 3)], (double)s);
    }

    // ---- Fence-free last-block epilogue (tid 0 only) ----
    if (tid != 0) return;
    unsigned t = atom_acqrel_inc(&g_ticket);   // acq_rel RMW: release our RED,
    if (t != gridDim.x - 1) return;            // acquire all prior releases

    double v[12];
#pragma unroll
    for (int k = 0; k < 12; k++) v[k] = __ldcg(&g_acc[k]);   // MLP=12, one L2 trip

    double t0 = (v[0] + v[1]) + (v[2] + v[3]);      // xz
    double t1 = (v[4] + v[5]) + (v[6] + v[7]);      // xx (upper)
    double t2 = (v[8] + v[9]) + (v[10] + v[11]);    // zz (upper)

    double inv = 1.0 / sqrt(2.0 * 3.14159265358979323846 * (double)ks[0]);
    double nn = (double)n * (double)n;
    double mxz = t0 * inv / nn;
    double mxx = (2.0 * t1 + (double)n) * inv / nn;   // upper*2 + diagonal (exp(0)=1)
    double mzz = (2.0 * t2 + (double)n) * inv / nn;
    double r = 0.5 * log(mxx * mzz + 1e-5) - log(mxz + 1e-5);
    out[6 * n] = (float)(r * (double)theta[0]);

    // Reset for the next graph replay (ordered before kernel completion).
#pragma unroll
    for (int k = 0; k < 12; k++) g_acc[k] = 0.0;
    g_ticket = 0;
}

extern "C" void kernel_launch(void* const* d_in, const int* in_sizes, int n_in,
                              void* d_out, int out_size) {
    const float* x     = (const float*)d_in[0];
    const float* z     = (const float*)d_in[1];
    const float* ks    = (const float*)d_in[2];
    const float* theta = (const float*)d_in[3];
    float* out = (float*)d_out;

    const int n = in_sizes[0] / 3;            // 8192
    const int iTiles = n / (THREADS * RPT);   // 16
    const int jSlabs = n / JT;                // 32
    const int tpj = iTiles * jSlabs;          // 512
    const int wedge = iTiles * (jSlabs + 1 - iTiles);   // 272

    pair_kernel<<<tpj + 2 * wedge, THREADS>>>(x, z, ks, theta, out, n);
}